// round 1
// baseline (speedup 1.0000x reference)
#include <cuda_runtime.h>
#include <math.h>

// GRU: T=512 steps, B=32 batch, D=1024 in, H=1024 hidden.
// Persistent-kernel design: 128 CTAs (1/SM), each owns 8 hidden units
// (= 24 gate columns). W slice lives in smem across all steps.
// Grid-wide sync via atomic spin barrier; h double-buffered in global.

#define TT   512
#define BB   32
#define DD   1024
#define HH   1024
#define NCTA 128
#define JT   8                 // hidden cols per CTA
#define NC   24                // gate cols per CTA (JT*3)
#define NTH  256
#define KPW  128               // k-range per warp (1024 / 8 warps)
#define HXPAD 1028             // padded row (floats) for h/x tile
#define WSROW 1028             // padded row (floats) for W slice
#define RSTRIDE 25             // b-stride in reduction buffer (bank-friendly)
#define REDW (32 * RSTRIDE)    // per-warp partial block (800 floats)

#define TBH (TT * BB * HH)
#define BH  (BB * HH)

#define SMEM_FLOATS (NC * WSROW + BB * HXPAD)     // 24672 + 32896 = 57568
#define SMEM_BYTES  (SMEM_FLOATS * 4)             // 230272 <= 232448 (227KB opt-in)

// Scratch: Gi[t][gcol][b]  (201 MB), h double buffer, barrier counter.
__device__ float g_Gi[(size_t)TT * 3 * HH * BB];
__device__ float g_h[2 * BB * HH];
__device__ unsigned int g_bar;

static __device__ __forceinline__ float sigmoidf_(float x) {
    return 1.0f / (1.0f + expf(-x));
}

// 32x24 output tile, K-split across 8 warps (this warp does k in [kw0, kw0+128)).
// Thread (lane): j6 = lane&7 -> 3 gate cols c0..c0+2 ; bq = lane>>3 -> b = bq+4i.
// ws layout: ws[c][k] padded rows (conflict-free float4 loads).
// hx layout: hx[b][k] padded rows (conflict-free float4 loads, b stride 1).
__device__ __forceinline__ void tile_gemm(const float* __restrict__ ws,
                                          const float* __restrict__ hx,
                                          int c0, int bq, int kw0,
                                          float (&acc)[8][3]) {
#pragma unroll
    for (int i = 0; i < 8; i++)
#pragma unroll
        for (int g = 0; g < 3; g++) acc[i][g] = 0.0f;

#pragma unroll 2
    for (int kk = 0; kk < KPW; kk += 4) {
        const int k = kw0 + kk;
        const float4 wv0 = *(const float4*)(ws + (c0 + 0) * WSROW + k);
        const float4 wv1 = *(const float4*)(ws + (c0 + 1) * WSROW + k);
        const float4 wv2 = *(const float4*)(ws + (c0 + 2) * WSROW + k);
#pragma unroll
        for (int i = 0; i < 8; i++) {
            const float4 hv = *(const float4*)(hx + (bq + 4 * i) * HXPAD + k);
            acc[i][0] = fmaf(hv.x, wv0.x, acc[i][0]);
            acc[i][0] = fmaf(hv.y, wv0.y, acc[i][0]);
            acc[i][0] = fmaf(hv.z, wv0.z, acc[i][0]);
            acc[i][0] = fmaf(hv.w, wv0.w, acc[i][0]);
            acc[i][1] = fmaf(hv.x, wv1.x, acc[i][1]);
            acc[i][1] = fmaf(hv.y, wv1.y, acc[i][1]);
            acc[i][1] = fmaf(hv.z, wv1.z, acc[i][1]);
            acc[i][1] = fmaf(hv.w, wv1.w, acc[i][1]);
            acc[i][2] = fmaf(hv.x, wv2.x, acc[i][2]);
            acc[i][2] = fmaf(hv.y, wv2.y, acc[i][2]);
            acc[i][2] = fmaf(hv.z, wv2.z, acc[i][2]);
            acc[i][2] = fmaf(hv.w, wv2.w, acc[i][2]);
        }
    }
}

__global__ void gru_init() {
    int i = blockIdx.x * blockDim.x + threadIdx.x;
    if (i == 0) g_bar = 0u;
    if (i < 2 * BH) g_h[i] = 0.0f;
}

__global__ void __launch_bounds__(NTH, 1) gru_persistent(
    const float* __restrict__ input, const float* __restrict__ paddings,
    const float* __restrict__ W_ih, const float* __restrict__ W_hh,
    const float* __restrict__ b_ih, const float* __restrict__ b_hh,
    float* __restrict__ out, int out_size)
{
    extern __shared__ float sm[];
    float* ws = sm;                     // [NC][WSROW] weight slice
    float* hx = sm + NC * WSROW;        // [BB][HXPAD] h or x tile
    float* red = hx;                    // reduction buffer overlays hx

    const int tid  = threadIdx.x;
    const int cta  = blockIdx.x;
    const int j0   = cta * JT;
    const int w    = tid >> 5;
    const int lane = tid & 31;
    const int j6   = lane & 7;
    const int bq   = lane >> 3;
    const int c0   = j6 * 3;
    const int kw0  = w * KPW;
    // gate-phase mapping: one thread <-> one (b, hidden j) pair
    const int gb = tid & 31;
    const int gj = tid >> 5;
    const int jg = j0 + gj;

    float bihr[3], bhhr[3];
#pragma unroll
    for (int g = 0; g < 3; g++) {
        bihr[g] = b_ih[g * HH + jg];
        bhhr[g] = b_hh[g * HH + jg];
    }

    // ---------------- Phase 1: Gi = X @ W_ih + b_ih (this CTA's 24 cols) ----
    for (int idx = tid; idx < NC * DD; idx += NTH) {
        int c = idx >> 10, k = idx & 1023;
        int g = c % 3, jl = c / 3;
        ws[c * WSROW + k] = W_ih[k * (3 * HH) + g * HH + j0 + jl];
    }
    __syncthreads();

#pragma unroll 1
    for (int t = 0; t < TT; t++) {
        const float4* src = (const float4*)(input + (size_t)t * BB * DD);
        for (int f = tid; f < (BB * DD) / 4; f += NTH) {
            float4 v = src[f];
            *(float4*)(hx + (f >> 8) * HXPAD + (f & 255) * 4) = v;
        }
        __syncthreads();

        float acc[8][3];
        tile_gemm(ws, hx, c0, bq, kw0, acc);
        __syncthreads();   // all reads of hx done; red overlays hx

#pragma unroll
        for (int i = 0; i < 8; i++)
#pragma unroll
            for (int g = 0; g < 3; g++)
                red[w * REDW + (bq + 4 * i) * RSTRIDE + c0 + g] = acc[i][g];
        __syncthreads();

#pragma unroll
        for (int g = 0; g < 3; g++) {
            float s = bihr[g];
#pragma unroll
            for (int ww = 0; ww < 8; ww++)
                s += red[ww * REDW + gb * RSTRIDE + gj * 3 + g];
            g_Gi[(size_t)t * (3 * HH * BB) + (size_t)(g * HH + jg) * BB + gb] = s;
        }
        __syncthreads();   // red reads done before next tile load
    }

    // ---------------- Load W_hh slice (replaces W_ih in smem) ---------------
    for (int idx = tid; idx < NC * DD; idx += NTH) {
        int c = idx >> 10, k = idx & 1023;
        int g = c % 3, jl = c / 3;
        ws[c * WSROW + k] = W_hh[k * (3 * HH) + g * HH + j0 + jl];
    }
    __syncthreads();

    // ---------------- Phase 2: sequential recurrence ------------------------
    unsigned int barnum = 0;
#pragma unroll 1
    for (int t = 0; t < TT; t++) {
        const int rb = t & 1;
        const float4* hsrc = (const float4*)(g_h + rb * BH);
        for (int f = tid; f < BH / 4; f += NTH) {
            float4 v = __ldcg(hsrc + f);   // L2-only: other CTAs wrote it
            *(float4*)(hx + (f >> 8) * HXPAD + (f & 255) * 4) = v;
        }
        __syncthreads();

        float acc[8][3];
        tile_gemm(ws, hx, c0, bq, kw0, acc);
        const float h_old = hx[gb * HXPAD + jg];   // before red overlays hx
        __syncthreads();

#pragma unroll
        for (int i = 0; i < 8; i++)
#pragma unroll
            for (int g = 0; g < 3; g++)
                red[w * REDW + (bq + 4 * i) * RSTRIDE + c0 + g] = acc[i][g];
        __syncthreads();

        float gh[3];
#pragma unroll
        for (int g = 0; g < 3; g++) {
            float s = bhhr[g];
#pragma unroll
            for (int ww = 0; ww < 8; ww++)
                s += red[ww * REDW + gb * RSTRIDE + gj * 3 + g];
            gh[g] = s;
        }

        const size_t gibase = (size_t)t * (3 * HH * BB) + (size_t)jg * BB + gb;
        const float gi0 = g_Gi[gibase];
        const float gi1 = g_Gi[gibase + (size_t)HH * BB];
        const float gi2 = g_Gi[gibase + (size_t)2 * HH * BB];

        const float r = sigmoidf_(gi0 + gh[0]);
        const float z = sigmoidf_(gi1 + gh[1]);
        const float n = tanhf(gi2 + r * gh[2]);
        float hn = (1.0f - z) * n + z * h_old;
        const float p = paddings[t * BB + gb];
        hn = p * h_old + (1.0f - p) * hn;

        out[(size_t)t * BH + gb * HH + jg] = hn;
        __stcg(&g_h[(1 - rb) * BH + gb * HH + jg], hn);
        if (t == TT - 1) {
            if (out_size >= TBH + BH)     out[TBH + gb * HH + jg] = hn;          // outputs[-1]
            if (out_size >= TBH + 2 * BH) out[TBH + BH + gb * HH + jg] = hn;     // h_last
        }

        // ---- grid barrier (release h writes, then arrive+spin) ----
        __threadfence();
        __syncthreads();
        barnum++;
        if (t != TT - 1) {
            if (tid == 0) {
                atomicAdd(&g_bar, 1u);
                const unsigned int target = barnum * NCTA;
                while (*((volatile unsigned int*)&g_bar) < target) { }
                __threadfence();
            }
            __syncthreads();
        }
    }
}

extern "C" void kernel_launch(void* const* d_in, const int* in_sizes, int n_in,
                              void* d_out, int out_size) {
    const float* input    = (const float*)d_in[0];
    const float* paddings = (const float*)d_in[1];
    const float* W_ih     = (const float*)d_in[2];
    const float* W_hh     = (const float*)d_in[3];
    const float* b_ih     = (const float*)d_in[4];
    const float* b_hh     = (const float*)d_in[5];
    float* out = (float*)d_out;

    cudaFuncSetAttribute(gru_persistent,
                         cudaFuncAttributeMaxDynamicSharedMemorySize, SMEM_BYTES);

    gru_init<<<(2 * BH + 255) / 256, 256>>>();
    gru_persistent<<<NCTA, NTH, SMEM_BYTES>>>(input, paddings, W_ih, W_hh,
                                              b_ih, b_hh, out, out_size);
}

// round 2
// speedup vs baseline: 1.0246x; 1.0246x over previous
#include <cuda_runtime.h>
#include <math.h>

// GRU T=512, B=32, D=H=1024, fp32. Persistent kernel, 147 CTAs (1/SM),
// each CTA owns 7 hidden units (21 gate cols). W slice cached in smem.
// GEMM mapping: lane = batch row b, 21 fp32 accumulators per thread,
// K split across 16 warps. h/x tile in smem with XOR-swizzled float4 rows.

#define TT   512
#define BB   32
#define DD   1024
#define HH   1024
#define NCTA 147
#define JT   7                  // hidden units per CTA
#define NC   21                 // gate cols per CTA
#define NTH  512
#define NW   16
#define KPW  64                 // K per warp (1024/16)
#define NCH  256                // float4 chunks per row (1024/4)
#define RSTR 23                 // reduction b-stride (floats), coprime w/ 32
#define REDW (32 * RSTR)        // per-warp reduction block

#define TBH (TT * BB * HH)
#define BH  (BB * HH)
#define G3H (3 * HH)

#define WS_FLOATS (NC * DD)             // 21504
#define HX_FLOATS (BB * DD)             // 32768
#define SMEM_FLOATS (WS_FLOATS + HX_FLOATS)
#define SMEM_BYTES  (SMEM_FLOATS * 4)   // 217088 <= 232448

__device__ float g_Gi[(size_t)TT * G3H * BB];
__device__ float g_h[2 * BB * HH];
__device__ unsigned int g_bar;

static __device__ __forceinline__ float sigmoidf_(float x) {
    return 1.0f / (1.0f + __expf(-x));
}

// GEMM: this thread computes partial dot over k in [kw0, kw0+KPW) for all
// NC gate cols of this CTA, batch row b = lane. ws[c][k] read as warp-wide
// broadcast float4; hx4 read with XOR swizzle (chunk ^ (b&7)) -> optimal LDS.128.
__device__ __forceinline__ void tile_gemm(const float* __restrict__ ws,
                                          const float4* __restrict__ hx4,
                                          int b, int kc0, float (&acc)[NC]) {
#pragma unroll
    for (int c = 0; c < NC; c++) acc[c] = 0.0f;
    const int xorm = b & 7;
    const float4* hrow = hx4 + b * NCH;
#pragma unroll 2
    for (int cc = 0; cc < KPW / 4; cc++) {
        const int kc = kc0 + cc;
        const float4 hv = hrow[kc ^ xorm];
        const int kf = kc * 4;
#pragma unroll
        for (int c = 0; c < NC; c++) {
            const float4 wv = *(const float4*)(ws + c * DD + kf);
            acc[c] = fmaf(hv.x, wv.x, acc[c]);
            acc[c] = fmaf(hv.y, wv.y, acc[c]);
            acc[c] = fmaf(hv.z, wv.z, acc[c]);
            acc[c] = fmaf(hv.w, wv.w, acc[c]);
        }
    }
}

__global__ void gru_init() {
    int i = blockIdx.x * blockDim.x + threadIdx.x;
    if (i == 0) g_bar = 0u;
    if (i < 2 * BH) g_h[i] = 0.0f;
}

__global__ void __launch_bounds__(NTH, 1) gru_persistent(
    const float* __restrict__ input, const float* __restrict__ paddings,
    const float* __restrict__ W_ih, const float* __restrict__ W_hh,
    const float* __restrict__ b_ih, const float* __restrict__ b_hh,
    float* __restrict__ out, int out_size)
{
    extern __shared__ float sm[];
    float* ws = sm;                         // [NC][DD]
    float4* hx4 = (float4*)(sm + WS_FLOATS);// [BB][NCH] swizzled
    float* hxf = sm + WS_FLOATS;
    float* red = hxf;                       // overlays hx after gemm

    const int tid  = threadIdx.x;
    const int cta  = blockIdx.x;
    const int j0   = cta * JT;
    const int w    = tid >> 5;
    const int b    = tid & 31;              // lane = batch row
    const int kw0  = w * KPW;
    const int kc0  = kw0 / 4;

    // gate-phase mapping: thread -> (batch gb, local hidden gj)
    const int gb = tid & 31;
    const int gj = tid >> 5;                // 0..15, active if gj < JT
    const int jg = j0 + gj;
    const bool gact = (gj < JT) && (jg < HH);
    const int jgc = (jg < HH) ? jg : (HH - 1);

    float bihr[3], bhhr[3];
#pragma unroll
    for (int g = 0; g < 3; g++) {
        bihr[g] = b_ih[g * HH + jgc];
        bhhr[g] = b_hh[g * HH + jgc];
    }

    // -------- Phase 1: Gi = X @ W_ih + b_ih (this CTA's 21 cols) --------
    for (int idx = tid; idx < NC * DD; idx += NTH) {
        int c = idx >> 10, k = idx & 1023;
        int g = c % 3, jl = c / 3;
        int j = j0 + jl; if (j >= HH) j = HH - 1;
        ws[c * DD + k] = W_ih[k * G3H + g * HH + j];
    }
    __syncthreads();

#pragma unroll 1
    for (int t = 0; t < TT; t++) {
        const float4* src = (const float4*)(input + (size_t)t * BB * DD);
        for (int f = tid; f < BB * NCH; f += NTH) {
            float4 v = src[f];
            int rb = f >> 8, c = f & 255;
            hx4[rb * NCH + (c ^ (rb & 7))] = v;
        }
        __syncthreads();

        float acc[NC];
        tile_gemm(ws, hx4, b, kc0, acc);
        __syncthreads();                    // hx reads done; red overlays

        {
            float* myred = red + w * REDW + b * RSTR;
#pragma unroll
            for (int c = 0; c < NC; c++) myred[c] = acc[c];
        }
        __syncthreads();

        if (gact) {
#pragma unroll
            for (int g = 0; g < 3; g++) {
                float s = bihr[g];
#pragma unroll
                for (int ww = 0; ww < NW; ww++)
                    s += red[ww * REDW + gb * RSTR + gj * 3 + g];
                g_Gi[(size_t)t * (G3H * BB) + (size_t)(g * HH + jg) * BB + gb] = s;
            }
        }
        __syncthreads();                    // red reads done before next tile
    }

    // -------- Load W_hh slice --------
    for (int idx = tid; idx < NC * DD; idx += NTH) {
        int c = idx >> 10, k = idx & 1023;
        int g = c % 3, jl = c / 3;
        int j = j0 + jl; if (j >= HH) j = HH - 1;
        ws[c * DD + k] = W_hh[k * G3H + g * HH + j];
    }
    __syncthreads();

    // -------- Phase 2: sequential recurrence --------
    unsigned int barnum = 0;
#pragma unroll 1
    for (int t = 0; t < TT; t++) {
        const int rb = t & 1;
        const float4* hsrc = (const float4*)(g_h + rb * BH);
        for (int f = tid; f < BB * NCH; f += NTH) {
            float4 v = __ldcg(hsrc + f);
            int rr = f >> 8, c = f & 255;
            hx4[rr * NCH + (c ^ (rr & 7))] = v;
        }
        __syncthreads();

        float acc[NC];
        tile_gemm(ws, hx4, b, kc0, acc);

        // read h_old before red overlays hx
        float h_old = 0.0f;
        if (gact) {
            int ch = (jgc >> 2) ^ (gb & 7);
            h_old = hxf[(gb * NCH + ch) * 4 + (jgc & 3)];
        }
        __syncthreads();

        {
            float* myred = red + w * REDW + b * RSTR;
#pragma unroll
            for (int c = 0; c < NC; c++) myred[c] = acc[c];
        }
        __syncthreads();

        if (gact) {
            float gh[3];
#pragma unroll
            for (int g = 0; g < 3; g++) {
                float s = bhhr[g];
#pragma unroll
                for (int ww = 0; ww < NW; ww++)
                    s += red[ww * REDW + gb * RSTR + gj * 3 + g];
                gh[g] = s;
            }

            const size_t gibase = (size_t)t * (G3H * BB) + (size_t)jg * BB + gb;
            const float gi0 = g_Gi[gibase];
            const float gi1 = g_Gi[gibase + (size_t)HH * BB];
            const float gi2 = g_Gi[gibase + (size_t)2 * HH * BB];

            const float r = sigmoidf_(gi0 + gh[0]);
            const float z = sigmoidf_(gi1 + gh[1]);
            const float n = tanhf(gi2 + r * gh[2]);
            float hn = (1.0f - z) * n + z * h_old;
            const float p = paddings[t * BB + gb];
            hn = p * h_old + (1.0f - p) * hn;

            out[(size_t)t * BH + gb * HH + jg] = hn;
            __stcg(&g_h[(1 - rb) * BH + gb * HH + jg], hn);
            if (t == TT - 1) {
                if (out_size >= TBH + BH)     out[TBH + gb * HH + jg] = hn;
                if (out_size >= TBH + 2 * BH) out[TBH + BH + gb * HH + jg] = hn;
            }
        }

        // ---- grid barrier ----
        __threadfence();
        __syncthreads();
        barnum++;
        if (t != TT - 1) {
            if (tid == 0) {
                atomicAdd(&g_bar, 1u);
                const unsigned int target = barnum * NCTA;
                while (*((volatile unsigned int*)&g_bar) < target) { }
                __threadfence();
            }
            __syncthreads();
        }
    }
}

extern "C" void kernel_launch(void* const* d_in, const int* in_sizes, int n_in,
                              void* d_out, int out_size) {
    const float* input    = (const float*)d_in[0];
    const float* paddings = (const float*)d_in[1];
    const float* W_ih     = (const float*)d_in[2];
    const float* W_hh     = (const float*)d_in[3];
    const float* b_ih     = (const float*)d_in[4];
    const float* b_hh     = (const float*)d_in[5];
    float* out = (float*)d_out;

    cudaFuncSetAttribute(gru_persistent,
                         cudaFuncAttributeMaxDynamicSharedMemorySize, SMEM_BYTES);

    gru_init<<<(2 * BH + 255) / 256, 256>>>();
    gru_persistent<<<NCTA, NTH, SMEM_BYTES>>>(input, paddings, W_ih, W_hh,
                                              b_ih, b_hh, out, out_size);
}

// round 4
// speedup vs baseline: 1.2685x; 1.2380x over previous
#include <cuda_runtime.h>
#include <math.h>
#include <stdint.h>

// GRU T=512, B=32, D=H=1024, fp32. Persistent kernel, 147 CTAs (1/SM), JT=7.
// f32x2 packed FMA, transposed [k][b] state tiles staged via cp.async.bulk
// with per-chunk mbarriers (4 x 32KB), W slice resident in smem.

#define TT   512
#define BB   32
#define DD   1024
#define HH   1024
#define NCTA 147
#define JT   7
#define NC   21
#define NTH  512
#define NW   16
#define KPW  64
#define NCHUNK 4
#define CHUNK_FLOATS 8192          // 32KB
#define RSTR 21
#define REDW (32 * RSTR)           // 672

#define TBH (TT * BB * HH)
#define BH  (BB * HH)
#define G3H (3 * HH)

#define WS_FLOATS (NC * DD)        // 21504 (84KB)
#define HX_FLOATS (BB * DD)        // 32768 (128KB)
#define SMEM_BYTES ((WS_FLOATS + HX_FLOATS) * 4)   // 217088

typedef unsigned long long u64;

__device__ float g_xT[(size_t)TT * BH];            // [t][k][b]
__device__ float g_WT[2][(size_t)G3H * DD];        // [m][c][k]
__device__ float g_Gi[(size_t)TT * NCTA * 3 * 224];
__device__ float g_h[2 * BH];                      // [buf][k][b]
__device__ unsigned int g_bar;

static __device__ __forceinline__ void fma2(u64 &d, u64 a, u64 b) {
    asm("fma.rn.f32x2 %0, %1, %2, %0;" : "+l"(d) : "l"(a), "l"(b));
}
static __device__ __forceinline__ u64 packf2(float lo, float hi) {
    u64 r; asm("mov.b64 %0, {%1, %2};" : "=l"(r) : "f"(lo), "f"(hi)); return r;
}
static __device__ __forceinline__ float2 unpackf2(u64 v) {
    float2 r; asm("mov.b64 {%0, %1}, %2;" : "=f"(r.x), "=f"(r.y) : "l"(v)); return r;
}
static __device__ __forceinline__ uint32_t smem_u32(const void* p) {
    uint32_t a;
    asm("{ .reg .u64 t; cvta.to.shared.u64 t, %1; cvt.u32.u64 %0, t; }" : "=r"(a) : "l"(p));
    return a;
}
static __device__ __forceinline__ void mbar_init(uint32_t mbar, uint32_t cnt) {
    asm volatile("mbarrier.init.shared.b64 [%0], %1;" :: "r"(mbar), "r"(cnt) : "memory");
}
static __device__ __forceinline__ void mbar_expect_tx(uint32_t mbar, uint32_t bytes) {
    asm volatile("mbarrier.arrive.expect_tx.shared.b64 _, [%0], %1;" :: "r"(mbar), "r"(bytes) : "memory");
}
static __device__ __forceinline__ void mbar_wait(uint32_t mbar, uint32_t parity) {
    uint32_t done;
    asm volatile("{\n\t.reg .pred p;\n\t"
                 "mbarrier.try_wait.parity.acquire.cta.shared::cta.b64 p, [%1], %2;\n\t"
                 "selp.b32 %0, 1, 0, p;\n\t}"
                 : "=r"(done) : "r"(mbar), "r"(parity) : "memory");
    if (!done) {
        asm volatile("{\n\t.reg .pred P1;\n\t"
                     "WL_%=:\n\t"
                     "mbarrier.try_wait.parity.acquire.cta.shared::cta.b64 P1, [%0], %1, 0x989680;\n\t"
                     "@P1 bra.uni WD_%=;\n\t"
                     "bra.uni WL_%=;\n\t"
                     "WD_%=:\n\t}"
                     :: "r"(mbar), "r"(parity) : "memory");
    }
}
static __device__ __forceinline__ void bulk_g2s(uint32_t dst, const void* src,
                                                uint32_t bytes, uint32_t mbar) {
    asm volatile("cp.async.bulk.shared::cta.global.mbarrier::complete_tx::bytes [%0], [%1], %2, [%3];"
                 :: "r"(dst), "l"(src), "r"(bytes), "r"(mbar) : "memory");
}
static __device__ __forceinline__ void fence_async() {
    asm volatile("fence.proxy.async;" ::: "memory");
}
static __device__ __forceinline__ float sigmoidf_(float x) {
    return 1.0f / (1.0f + __expf(-x));
}

// ---------------- prep kernels ----------------
__global__ void wtrans_kernel(const float* __restrict__ W0, const float* __restrict__ W1) {
    __shared__ float s[32][33];
    const float* W = blockIdx.z ? W1 : W0;
    float* WT = g_WT[blockIdx.z];
    int c0 = blockIdx.y * 32, k0 = blockIdx.x * 32;
    int tx = threadIdx.x, ty = threadIdx.y;
#pragma unroll
    for (int i = 0; i < 32; i += 8)
        s[ty + i][tx] = W[(size_t)(k0 + ty + i) * G3H + c0 + tx];
    __syncthreads();
#pragma unroll
    for (int i = 0; i < 32; i += 8)
        WT[(size_t)(c0 + ty + i) * DD + k0 + tx] = s[tx][ty + i];
}

__global__ void xtrans_kernel(const float* __restrict__ input) {
    __shared__ float s[32][33];
    int t = blockIdx.y, k0 = blockIdx.x * 32;
    int tx = threadIdx.x, ty = threadIdx.y;
    const float* xin = input + (size_t)t * BH;
    float* xo = g_xT + (size_t)t * BH;
#pragma unroll
    for (int i = 0; i < 32; i += 8)
        s[ty + i][tx] = xin[(size_t)(ty + i) * DD + k0 + tx];
    __syncthreads();
#pragma unroll
    for (int i = 0; i < 32; i += 8)
        xo[(size_t)(k0 + ty + i) * BB + tx] = s[tx][ty + i];
}

__global__ void zero_kernel() {
    int i = blockIdx.x * blockDim.x + threadIdx.x;
    if (i == 0) g_bar = 0u;
    if (i < 2 * BH) g_h[i] = 0.0f;
}

// ---------------- GEMM tile ----------------
// hxf layout [k][BB]; warp covers k in [k0, k0+KPW); lane = b.
__device__ __forceinline__ void tile_gemm(const float* __restrict__ ws,
                                          const float* __restrict__ hxf,
                                          int b, int k0, u64 (&acc)[NC]) {
#pragma unroll
    for (int c = 0; c < NC; c++) acc[c] = 0ULL;
    const float* hb = hxf + (size_t)k0 * BB + b;
    const float* wk = ws + k0;
#pragma unroll 1
    for (int kk = 0; kk < KPW; kk += 16) {
#pragma unroll
        for (int u = 0; u < 16; u += 4) {
            const int k = kk + u;
            const float h0 = hb[(k + 0) * BB];
            const float h1 = hb[(k + 1) * BB];
            const float h2 = hb[(k + 2) * BB];
            const float h3 = hb[(k + 3) * BB];
            const u64 hp0 = packf2(h0, h1);
            const u64 hp1 = packf2(h2, h3);
#pragma unroll
            for (int c = 0; c < NC; c++) {
                const ulonglong2 wv = *(const ulonglong2*)(wk + c * DD + k);
                fma2(acc[c], hp0, wv.x);
                fma2(acc[c], hp1, wv.y);
            }
        }
    }
}

// ---------------- main persistent kernel ----------------
__global__ void __launch_bounds__(NTH, 1) gru_persistent(
    const float* __restrict__ paddings,
    const float* __restrict__ b_ih, const float* __restrict__ b_hh,
    float* __restrict__ out, int out_size)
{
    extern __shared__ float sm[];
    float* ws = sm;                       // [NC][DD]
    float* hxf = sm + WS_FLOATS;          // [DD][BB]
    float* red = hxf;                     // overlays hx (lifetime disjoint)
    __shared__ __align__(8) u64 mbars[NCHUNK];

    const int tid  = threadIdx.x;
    const int cta  = blockIdx.x;
    const int j0   = cta * JT;
    const int w    = tid >> 5;
    const int b    = tid & 31;
    const int k0   = w * KPW;
    const int mychunk = w >> 2;

    const int gb = tid & 31;
    const int gj = tid >> 5;
    const int jg = j0 + gj;
    const bool gact = (gj < JT) && (jg < HH);
    const int jgc = (jg < HH) ? jg : (HH - 1);

    uint32_t mb[NCHUNK];
#pragma unroll
    for (int c = 0; c < NCHUNK; c++) mb[c] = smem_u32(&mbars[c]);
    const uint32_t hx_s = smem_u32(hxf);

    if (tid == 0) {
#pragma unroll
        for (int c = 0; c < NCHUNK; c++) mbar_init(mb[c], 1);
    }

    float bihr[3], bhhr[3];
#pragma unroll
    for (int g = 0; g < 3; g++) {
        bihr[g] = b_ih[g * HH + jgc];
        bhhr[g] = b_hh[g * HH + jgc];
    }

    // load W_ih slice: ws[c][k] = WT0[g*HH + j0 + jl][k], c = jl*3+g
    {
        const float* WT0 = g_WT[0];
        for (int idx = tid; idx < NC * (DD / 4); idx += NTH) {
            int c = idx >> 8, q = idx & 255;
            int g = c % 3, jl = c / 3;
            int j = j0 + jl; if (j > HH - 1) j = HH - 1;
            ((float4*)(ws + c * DD))[q] =
                ((const float4*)(WT0 + (size_t)(g * HH + j) * DD))[q];
        }
    }
    __syncthreads();   // mbar init + ws visible

    int pc = 0;

    // ================= Phase 1: Gi = X @ W_ih + b_ih =================
#pragma unroll 1
    for (int t = 0; t < TT; t++) {
        if (tid == 0) {
            fence_async();
            const float* src = g_xT + (size_t)t * BH;
#pragma unroll
            for (int c = 0; c < NCHUNK; c++) {
                mbar_expect_tx(mb[c], CHUNK_FLOATS * 4);
                bulk_g2s(hx_s + c * CHUNK_FLOATS * 4, src + c * CHUNK_FLOATS,
                         CHUNK_FLOATS * 4, mb[c]);
            }
        }
        mbar_wait(mb[mychunk], pc & 1);

        u64 acc[NC];
        tile_gemm(ws, hxf, b, k0, acc);
        __syncthreads();                   // all gemm reads done; red safe

        {
            float* myred = red + w * REDW + b * RSTR;
#pragma unroll
            for (int c = 0; c < NC; c++) {
                float2 u = unpackf2(acc[c]);
                myred[c] = u.x + u.y;
            }
        }
        __syncthreads();

        if (gact) {
            float* gdst = g_Gi + ((size_t)t * NCTA + cta) * (3 * 224);
#pragma unroll
            for (int g = 0; g < 3; g++) {
                float s = bihr[g];
#pragma unroll
                for (int ww = 0; ww < NW; ww++)
                    s += red[ww * REDW + gb * RSTR + gj * 3 + g];
                gdst[g * 224 + tid] = s;
            }
        }
        __syncthreads();                   // red reads done before next bulks
        pc++;
    }

    // swap ws to W_hh
    {
        const float* WT1 = g_WT[1];
        for (int idx = tid; idx < NC * (DD / 4); idx += NTH) {
            int c = idx >> 8, q = idx & 255;
            int g = c % 3, jl = c / 3;
            int j = j0 + jl; if (j > HH - 1) j = HH - 1;
            ((float4*)(ws + c * DD))[q] =
                ((const float4*)(WT1 + (size_t)(g * HH + j) * DD))[q];
        }
    }
    __syncthreads();

    // ================= Phase 2: recurrence =================
    float h_old = 0.0f;
#pragma unroll 1
    for (int t = 0; t < TT; t++) {
        const int rb = t & 1;
        if (tid == 0) {
            fence_async();
            const float* src = g_h + rb * BH;
#pragma unroll
            for (int c = 0; c < NCHUNK; c++) {
                mbar_expect_tx(mb[c], CHUNK_FLOATS * 4);
                bulk_g2s(hx_s + c * CHUNK_FLOATS * 4, src + c * CHUNK_FLOATS,
                         CHUNK_FLOATS * 4, mb[c]);
            }
        }

        // prefetch Gi + padding (latency hidden behind gemm)
        float gi0 = 0.f, gi1 = 0.f, gi2 = 0.f, p = 0.f;
        if (gact) {
            const float* gsrc = g_Gi + ((size_t)t * NCTA + cta) * (3 * 224);
            gi0 = gsrc[0 * 224 + tid];
            gi1 = gsrc[1 * 224 + tid];
            gi2 = gsrc[2 * 224 + tid];
            p   = paddings[t * BB + gb];
        }

        mbar_wait(mb[mychunk], pc & 1);

        u64 acc[NC];
        tile_gemm(ws, hxf, b, k0, acc);
        __syncthreads();

        {
            float* myred = red + w * REDW + b * RSTR;
#pragma unroll
            for (int c = 0; c < NC; c++) {
                float2 u = unpackf2(acc[c]);
                myred[c] = u.x + u.y;
            }
        }
        __syncthreads();

        if (gact) {
            float gh[3];
#pragma unroll
            for (int g = 0; g < 3; g++) {
                float s = bhhr[g];
#pragma unroll
                for (int ww = 0; ww < NW; ww++)
                    s += red[ww * REDW + gb * RSTR + gj * 3 + g];
                gh[g] = s;
            }

            const float r = sigmoidf_(gi0 + gh[0]);
            const float z = sigmoidf_(gi1 + gh[1]);
            const float n = tanhf(gi2 + r * gh[2]);
            float hn = (1.0f - z) * n + z * h_old;
            hn = p * h_old + (1.0f - p) * hn;
            h_old = hn;

            out[(size_t)t * BH + gb * HH + jg] = hn;
            __stcg(&g_h[(1 - rb) * BH + jg * BB + gb], hn);
            if (t == TT - 1) {
                if (out_size >= TBH + BH)     out[TBH + gb * HH + jg] = hn;
                if (out_size >= TBH + 2 * BH) out[TBH + BH + gb * HH + jg] = hn;
            }
        }

        __threadfence();
        __syncthreads();
        pc++;

        if (t != TT - 1) {
            if (tid == 0) {
                atomicAdd(&g_bar, 1u);
                const unsigned int target = (unsigned int)(t + 1) * NCTA;
                while (*((volatile unsigned int*)&g_bar) < target) {
                    __nanosleep(64);
                }
                __threadfence();
            }
            __syncthreads();
        }
    }
}

extern "C" void kernel_launch(void* const* d_in, const int* in_sizes, int n_in,
                              void* d_out, int out_size) {
    const float* input    = (const float*)d_in[0];
    const float* paddings = (const float*)d_in[1];
    const float* W_ih     = (const float*)d_in[2];
    const float* W_hh     = (const float*)d_in[3];
    const float* b_ih     = (const float*)d_in[4];
    const float* b_hh     = (const float*)d_in[5];
    float* out = (float*)d_out;

    cudaFuncSetAttribute(gru_persistent,
                         cudaFuncAttributeMaxDynamicSharedMemorySize, SMEM_BYTES);

    {
        dim3 blk(32, 8);
        dim3 grd(DD / 32, G3H / 32, 2);
        wtrans_kernel<<<grd, blk>>>(W_ih, W_hh);
    }
    {
        dim3 blk(32, 8);
        dim3 grd(DD / 32, TT);
        xtrans_kernel<<<grd, blk>>>(input);
    }
    zero_kernel<<<(2 * BH + 255) / 256, 256>>>();

    gru_persistent<<<NCTA, NTH, SMEM_BYTES>>>(paddings, b_ih, b_hh, out, out_size);
}

// round 8
// speedup vs baseline: 1.3660x; 1.0769x over previous
#include <cuda_runtime.h>
#include <math.h>
#include <stdint.h>

// GRU T=512, B=32, D=H=1024, fp32. Persistent kernel, 147 CTAs (1/SM), JT=7.
// f32x2 packed FMA. h/x read DIRECTLY from L2 via __ldcg inside the GEMM
// (no smem staging): the 128KB/step broadcast overlaps the FFMA2 stream.
// W slice (84KB) resident in smem; dedicated reduction buffer (43KB).

#define TT   512
#define BB   32
#define DD   1024
#define HH   1024
#define NCTA 147
#define JT   7
#define NC   21
#define NTH  512
#define NW   16
#define KPW  64                    // K per warp (1024/16)
#define RSTR 21
#define REDW (32 * RSTR)           // 672 floats per warp

#define TBH (TT * BB * HH)
#define BH  (BB * HH)
#define G3H (3 * HH)

#define WS_FLOATS  (NC * DD)                   // 21504
#define RED_FLOATS (NW * REDW)                 // 10752
#define SMEM_BYTES ((WS_FLOATS + RED_FLOATS) * 4)  // 129024

typedef unsigned long long u64;

__device__ float g_xT[(size_t)TT * BH];        // [t][k][b]
__device__ float g_WT[2][(size_t)G3H * DD];    // [m][c][k]
__device__ float g_Gi[(size_t)TT * NCTA * 3 * 224];
__device__ float g_h[2 * BH];                  // [buf][k][b]
__device__ unsigned int g_bar;

static __device__ __forceinline__ void fma2(u64 &d, u64 a, u64 b) {
    asm("fma.rn.f32x2 %0, %1, %2, %0;" : "+l"(d) : "l"(a), "l"(b));
}
static __device__ __forceinline__ u64 packf2(float lo, float hi) {
    u64 r; asm("mov.b64 %0, {%1, %2};" : "=l"(r) : "f"(lo), "f"(hi)); return r;
}
static __device__ __forceinline__ float2 unpackf2(u64 v) {
    float2 r; asm("mov.b64 {%0, %1}, %2;" : "=f"(r.x), "=f"(r.y) : "l"(v)); return r;
}
static __device__ __forceinline__ float sigmoidf_(float x) {
    return 1.0f / (1.0f + __expf(-x));
}

// ---------------- prep kernels ----------------
__global__ void wtrans_kernel(const float* __restrict__ W0, const float* __restrict__ W1) {
    __shared__ float s[32][33];
    const float* W = blockIdx.z ? W1 : W0;
    float* WT = g_WT[blockIdx.z];
    int c0 = blockIdx.y * 32, k0 = blockIdx.x * 32;
    int tx = threadIdx.x, ty = threadIdx.y;
#pragma unroll
    for (int i = 0; i < 32; i += 8)
        s[ty + i][tx] = W[(size_t)(k0 + ty + i) * G3H + c0 + tx];
    __syncthreads();
#pragma unroll
    for (int i = 0; i < 32; i += 8)
        WT[(size_t)(c0 + ty + i) * DD + k0 + tx] = s[tx][ty + i];
}

__global__ void xtrans_kernel(const float* __restrict__ input) {
    __shared__ float s[32][33];
    int t = blockIdx.y, k0 = blockIdx.x * 32;
    int tx = threadIdx.x, ty = threadIdx.y;
    const float* xin = input + (size_t)t * BH;
    float* xo = g_xT + (size_t)t * BH;
#pragma unroll
    for (int i = 0; i < 32; i += 8)
        s[ty + i][tx] = xin[(size_t)(ty + i) * DD + k0 + tx];
    __syncthreads();
#pragma unroll
    for (int i = 0; i < 32; i += 8)
        xo[(size_t)(k0 + ty + i) * BB + tx] = s[tx][ty + i];
}

__global__ void zero_kernel() {
    int i = blockIdx.x * blockDim.x + threadIdx.x;
    if (i == 0) g_bar = 0u;
    if (i < 2 * BH) g_h[i] = 0.0f;
}

// ---------------- GEMM tile ----------------
// h/x read straight from global (L2) — layout [k][b], lane = b, coalesced.
// W from smem: ws[c][k], warp-wide broadcast LDS.128.
__device__ __forceinline__ void tile_gemm(const float* __restrict__ ws,
                                          const float* __restrict__ hg,
                                          int b, int k0, u64 (&acc)[NC]) {
#pragma unroll
    for (int c = 0; c < NC; c++) acc[c] = 0ULL;
    const float* hb = hg + (size_t)k0 * BB + b;
    const float* wk = ws + k0;
#pragma unroll 1
    for (int kk = 0; kk < KPW; kk += 16) {
        float hv[16];
#pragma unroll
        for (int u = 0; u < 16; u++)            // 16 batched L2 loads (MLP)
            hv[u] = __ldcg(hb + (kk + u) * BB);
#pragma unroll
        for (int u = 0; u < 16; u += 4) {
            const u64 hp0 = packf2(hv[u + 0], hv[u + 1]);
            const u64 hp1 = packf2(hv[u + 2], hv[u + 3]);
#pragma unroll
            for (int c = 0; c < NC; c++) {
                const ulonglong2 wv = *(const ulonglong2*)(wk + c * DD + kk + u);
                fma2(acc[c], hp0, wv.x);
                fma2(acc[c], hp1, wv.y);
            }
        }
    }
}

// ---------------- main persistent kernel ----------------
__global__ void __launch_bounds__(NTH, 1) gru_persistent(
    const float* __restrict__ paddings,
    const float* __restrict__ b_ih, const float* __restrict__ b_hh,
    float* __restrict__ out, int out_size)
{
    extern __shared__ float sm[];
    float* ws  = sm;                    // [NC][DD]
    float* red = sm + WS_FLOATS;        // [NW][REDW] dedicated

    const int tid = threadIdx.x;
    const int cta = blockIdx.x;
    const int j0  = cta * JT;
    const int w   = tid >> 5;
    const int b   = tid & 31;
    const int k0  = w * KPW;

    const int gb = tid & 31;
    const int gj = tid >> 5;
    const int jg = j0 + gj;
    const bool gact = (gj < JT) && (jg < HH);
    const int jgc = (jg < HH) ? jg : (HH - 1);

    float bihr[3], bhhr[3];
#pragma unroll
    for (int g = 0; g < 3; g++) {
        bihr[g] = b_ih[g * HH + jgc];
        bhhr[g] = b_hh[g * HH + jgc];
    }

    // load W_ih slice: ws[c][k], c = jl*3 + g
    {
        const float* WT0 = g_WT[0];
        for (int idx = tid; idx < NC * (DD / 4); idx += NTH) {
            int c = idx >> 8, q = idx & 255;
            int g = c % 3, jl = c / 3;
            int j = j0 + jl; if (j > HH - 1) j = HH - 1;
            ((float4*)(ws + c * DD))[q] =
                ((const float4*)(WT0 + (size_t)(g * HH + j) * DD))[q];
        }
    }
    __syncthreads();

    // ================= Phase 1: Gi = X @ W_ih + b_ih =================
#pragma unroll 1
    for (int t = 0; t < TT; t++) {
        u64 acc[NC];
        tile_gemm(ws, g_xT + (size_t)t * BH, b, k0, acc);

        {
            float* myred = red + w * REDW + b * RSTR;
#pragma unroll
            for (int c = 0; c < NC; c++) {
                float2 u = unpackf2(acc[c]);
                myred[c] = u.x + u.y;
            }
        }
        __syncthreads();

        if (gact) {
            float* gdst = g_Gi + ((size_t)t * NCTA + cta) * (3 * 224);
#pragma unroll
            for (int g = 0; g < 3; g++) {
                float s = bihr[g];
#pragma unroll
                for (int ww = 0; ww < NW; ww++)
                    s += red[ww * REDW + gb * RSTR + gj * 3 + g];
                __stcg(&gdst[g * 224 + tid], s);
            }
        }
        __syncthreads();           // red reads done before next step's writes
    }

    // swap ws to W_hh
    {
        const float* WT1 = g_WT[1];
        for (int idx = tid; idx < NC * (DD / 4); idx += NTH) {
            int c = idx >> 8, q = idx & 255;
            int g = c % 3, jl = c / 3;
            int j = j0 + jl; if (j > HH - 1) j = HH - 1;
            ((float4*)(ws + c * DD))[q] =
                ((const float4*)(WT1 + (size_t)(g * HH + j) * DD))[q];
        }
    }
    __syncthreads();

    // ================= Phase 2: recurrence =================
    float h_old = 0.0f;
#pragma unroll 1
    for (int t = 0; t < TT; t++) {
        const int rb = t & 1;

        // prefetch Gi + padding (hidden behind gemm)
        float gi0 = 0.f, gi1 = 0.f, gi2 = 0.f, p = 0.f;
        if (gact) {
            const float* gsrc = g_Gi + ((size_t)t * NCTA + cta) * (3 * 224);
            gi0 = __ldcg(&gsrc[0 * 224 + tid]);
            gi1 = __ldcg(&gsrc[1 * 224 + tid]);
            gi2 = __ldcg(&gsrc[2 * 224 + tid]);
            p   = paddings[t * BB + gb];
        }

        u64 acc[NC];
        tile_gemm(ws, g_h + rb * BH, b, k0, acc);

        {
            float* myred = red + w * REDW + b * RSTR;
#pragma unroll
            for (int c = 0; c < NC; c++) {
                float2 u = unpackf2(acc[c]);
                myred[c] = u.x + u.y;
            }
        }
        __syncthreads();

        if (gact) {
            float gh[3];
#pragma unroll
            for (int g = 0; g < 3; g++) {
                float s = bhhr[g];
#pragma unroll
                for (int ww = 0; ww < NW; ww++)
                    s += red[ww * REDW + gb * RSTR + gj * 3 + g];
                gh[g] = s;
            }

            const float r = sigmoidf_(gi0 + gh[0]);
            const float z = sigmoidf_(gi1 + gh[1]);
            const float n = tanhf(gi2 + r * gh[2]);
            float hn = (1.0f - z) * n + z * h_old;
            hn = p * h_old + (1.0f - p) * hn;
            h_old = hn;

            out[(size_t)t * BH + gb * HH + jg] = hn;
            __stcg(&g_h[(1 - rb) * BH + jg * BB + gb], hn);   // coalesced per warp
            if (t == TT - 1) {
                if (out_size >= TBH + BH)     out[TBH + gb * HH + jg] = hn;
                if (out_size >= TBH + 2 * BH) out[TBH + BH + gb * HH + jg] = hn;
            }
        }

        // ---- grid barrier (release h writes, arrive + spin) ----
        __threadfence();
        __syncthreads();
        if (t != TT - 1) {
            if (tid == 0) {
                atomicAdd(&g_bar, 1u);
                const unsigned int target = (unsigned int)(t + 1) * NCTA;
                while (*((volatile unsigned int*)&g_bar) < target) {
                    __nanosleep(32);
                }
                __threadfence();
            }
            __syncthreads();
        }
    }
}

extern "C" void kernel_launch(void* const* d_in, const int* in_sizes, int n_in,
                              void* d_out, int out_size) {
    const float* input    = (const float*)d_in[0];
    const float* paddings = (const float*)d_in[1];
    const float* W_ih     = (const float*)d_in[2];
    const float* W_hh     = (const float*)d_in[3];
    const float* b_ih     = (const float*)d_in[4];
    const float* b_hh     = (const float*)d_in[5];
    float* out = (float*)d_out;

    cudaFuncSetAttribute(gru_persistent,
                         cudaFuncAttributeMaxDynamicSharedMemorySize, SMEM_BYTES);

    {
        dim3 blk(32, 8);
        dim3 grd(DD / 32, G3H / 32, 2);
        wtrans_kernel<<<grd, blk>>>(W_ih, W_hh);
    }
    {
        dim3 blk(32, 8);
        dim3 grd(DD / 32, TT);
        xtrans_kernel<<<grd, blk>>>(input);
    }
    zero_kernel<<<(2 * BH + 255) / 256, 256>>>();

    gru_persistent<<<NCTA, NTH, SMEM_BYTES>>>(paddings, b_ih, b_hh, out, out_size);
}